// round 1
// baseline (speedup 1.0000x reference)
#include <cuda_runtime.h>
#include <math.h>
#include <stdint.h>

#define TTOK 2048
#define HDIM 1024
#define ENUM 8
#define IDIM 4096
#define VDIM 32000
#define KTOP 2

// ---- static scratch (no allocation allowed) ----
__device__ float g_x[(size_t)TTOK * HDIM];               // 8 MB  gathered embeddings
__device__ float g_h[(size_t)ENUM * TTOK * IDIM];        // 256 MB expert hidden
__device__ float g_eo[(size_t)TTOK * HDIM];              // 8 MB  combined expert output
__device__ int   g_sel[TTOK * KTOP];
__device__ int   g_list[ENUM][TTOK];
__device__ int   g_cnt[ENUM];

// ---------------- setup: gather + router + top2 + softmax ----------------
__global__ void setup_kernel(const int* __restrict__ ids,
                             const float* __restrict__ emb,
                             const float* __restrict__ rw,
                             const float* __restrict__ rb,
                             float* __restrict__ out_rw,
                             float* __restrict__ out_se) {
    int t = blockIdx.x;
    int tid = threadIdx.x;
    int row = ids[t];
    const float* src = emb + (size_t)row * HDIM;
    const float4* s4 = (const float4*)src;
    float4* d4 = (float4*)(g_x + (size_t)t * HDIM);
    for (int i = tid; i < HDIM / 4; i += blockDim.x) d4[i] = s4[i];

    float acc[ENUM];
#pragma unroll
    for (int e = 0; e < ENUM; e++) acc[e] = 0.f;
    for (int k = tid; k < HDIM; k += blockDim.x) {
        float xv = src[k];
        const float* wr = rw + (size_t)k * ENUM;
#pragma unroll
        for (int e = 0; e < ENUM; e++) acc[e] = fmaf(xv, wr[e], acc[e]);
    }
    __shared__ float sred[ENUM][128];
#pragma unroll
    for (int e = 0; e < ENUM; e++) sred[e][tid] = acc[e];
    __syncthreads();
    for (int s = 64; s > 0; s >>= 1) {
        if (tid < s) {
#pragma unroll
            for (int e = 0; e < ENUM; e++) sred[e][tid] += sred[e][tid + s];
        }
        __syncthreads();
    }
    if (tid == 0) {
        float lg[ENUM];
#pragma unroll
        for (int e = 0; e < ENUM; e++) lg[e] = sred[e][0] + rb[e];
        int i0 = 0; float v0 = lg[0];
#pragma unroll
        for (int e = 1; e < ENUM; e++) if (lg[e] > v0) { v0 = lg[e]; i0 = e; }
        int i1 = -1; float v1 = -3.0e38f;
#pragma unroll
        for (int e = 0; e < ENUM; e++) if (e != i0 && lg[e] > v1) { v1 = lg[e]; i1 = e; }
        float ee = expf(v1 - v0);
        float denom = 1.0f + ee;
        float w0 = 1.0f / denom;
        float w1 = ee / denom;
        g_sel[t * 2 + 0] = i0;
        g_sel[t * 2 + 1] = i1;
        if (out_rw) { out_rw[t * 2 + 0] = w0; out_rw[t * 2 + 1] = w1; }
        if (out_se) { out_se[t * 2 + 0] = (float)i0; out_se[t * 2 + 1] = (float)i1; }
    }
}

// ------------- deterministic per-expert token compaction -------------
__global__ void build_lists_kernel() {
    int e = blockIdx.x;
    int tid = threadIdx.x;
    int lane = tid & 31, wid = tid >> 5;
    __shared__ int wtot[8];
    __shared__ int s_base;
    if (tid == 0) s_base = 0;
    __syncthreads();
    for (int base = 0; base < TTOK; base += 256) {
        int t = base + tid;
        int f = (g_sel[t * 2] == e || g_sel[t * 2 + 1] == e) ? 1 : 0;
        unsigned bal = __ballot_sync(0xffffffffu, f);
        int lpfx = __popc(bal & ((1u << lane) - 1u));
        if (lane == 0) wtot[wid] = __popc(bal);
        __syncthreads();
        int woff = 0;
        for (int w = 0; w < wid; w++) woff += wtot[w];
        if (f) g_list[e][s_base + woff + lpfx] = t;
        int tot = 0;
        for (int w = 0; w < 8; w++) tot += wtot[w];
        __syncthreads();
        if (tid == 0) s_base += tot;
        __syncthreads();
    }
    if (tid == 0) g_cnt[e] = s_base;
}

__global__ void zero_eo_kernel() {
    size_t i = (size_t)blockIdx.x * blockDim.x + threadIdx.x;
    if (i < (size_t)TTOK * HDIM / 4) {
        float4 z = make_float4(0.f, 0.f, 0.f, 0.f);
        ((float4*)g_eo)[i] = z;
    }
}

// ---------------- FFN layer 1: gelu(Xg @ w1[e] + b1[e]) ----------------
__global__ __launch_bounds__(256, 2) void ffn1_kernel(const float* __restrict__ w1,
                                                      const float* __restrict__ b1) {
    int e = blockIdx.z;
    int cnt = g_cnt[e];
    int m0 = blockIdx.y * 128;
    if (m0 >= cnt) return;
    int n0 = blockIdx.x * 128;
    const float* B = w1 + (size_t)e * HDIM * IDIM;   // [H][I]
    __shared__ float As[8][128];
    __shared__ float Bs[8][128];
    int tid = threadIdx.x;
    int a_m = tid >> 1;
    int a_k = (tid & 1) * 4;
    int b_k = tid >> 5;
    int b_n = (tid & 31) * 4;
    int tr = tid >> 4;
    int tc = tid & 15;
    const float* a_src = nullptr;
    int gm = m0 + a_m;
    if (gm < cnt) {
        int tok = g_list[e][gm];
        a_src = g_x + (size_t)tok * HDIM + a_k;
    }
    float acc[8][8];
#pragma unroll
    for (int i = 0; i < 8; i++)
#pragma unroll
        for (int j = 0; j < 8; j++) acc[i][j] = 0.f;

    for (int k0 = 0; k0 < HDIM; k0 += 8) {
        float4 av = a_src ? *(const float4*)(a_src + k0) : make_float4(0.f, 0.f, 0.f, 0.f);
        As[a_k + 0][a_m] = av.x; As[a_k + 1][a_m] = av.y;
        As[a_k + 2][a_m] = av.z; As[a_k + 3][a_m] = av.w;
        *(float4*)&Bs[b_k][b_n] = *(const float4*)(B + (size_t)(k0 + b_k) * IDIM + n0 + b_n);
        __syncthreads();
#pragma unroll
        for (int kk = 0; kk < 8; kk++) {
            float af[8], bf[8];
#pragma unroll
            for (int i = 0; i < 8; i++) af[i] = As[kk][tr * 8 + i];
#pragma unroll
            for (int j = 0; j < 8; j++) bf[j] = Bs[kk][tc * 8 + j];
#pragma unroll
            for (int i = 0; i < 8; i++)
#pragma unroll
                for (int j = 0; j < 8; j++) acc[i][j] = fmaf(af[i], bf[j], acc[i][j]);
        }
        __syncthreads();
    }
    const float* b1e = b1 + (size_t)e * IDIM + n0;
#pragma unroll
    for (int i = 0; i < 8; i++) {
        int m = m0 + tr * 8 + i;
        if (m >= cnt) continue;
        float* dst = g_h + ((size_t)e * TTOK + m) * IDIM + n0;
#pragma unroll
        for (int j = 0; j < 8; j++) {
            int n = tc * 8 + j;
            float v = acc[i][j] + b1e[n];
            v = 0.5f * v * (1.0f + erff(v * 0.70710678118654752f));
            dst[n] = v;
        }
    }
}

// ---------------- FFN layer 2: H @ w2[e] + b2[e], atomic combine ----------------
__global__ __launch_bounds__(256, 2) void ffn2_kernel(const float* __restrict__ w2,
                                                      const float* __restrict__ b2) {
    int e = blockIdx.z;
    int cnt = g_cnt[e];
    int m0 = blockIdx.y * 128;
    if (m0 >= cnt) return;
    int n0 = blockIdx.x * 128;
    const float* B = w2 + (size_t)e * IDIM * HDIM;   // [I][H]
    __shared__ float As[8][128];
    __shared__ float Bs[8][128];
    int tid = threadIdx.x;
    int a_m = tid >> 1;
    int a_k = (tid & 1) * 4;
    int b_k = tid >> 5;
    int b_n = (tid & 31) * 4;
    int tr = tid >> 4;
    int tc = tid & 15;
    const float* a_src = nullptr;
    int gm = m0 + a_m;
    if (gm < cnt) a_src = g_h + ((size_t)e * TTOK + gm) * IDIM + a_k;

    float acc[8][8];
#pragma unroll
    for (int i = 0; i < 8; i++)
#pragma unroll
        for (int j = 0; j < 8; j++) acc[i][j] = 0.f;

    for (int k0 = 0; k0 < IDIM; k0 += 8) {
        float4 av = a_src ? *(const float4*)(a_src + k0) : make_float4(0.f, 0.f, 0.f, 0.f);
        As[a_k + 0][a_m] = av.x; As[a_k + 1][a_m] = av.y;
        As[a_k + 2][a_m] = av.z; As[a_k + 3][a_m] = av.w;
        *(float4*)&Bs[b_k][b_n] = *(const float4*)(B + (size_t)(k0 + b_k) * HDIM + n0 + b_n);
        __syncthreads();
#pragma unroll
        for (int kk = 0; kk < 8; kk++) {
            float af[8], bf[8];
#pragma unroll
            for (int i = 0; i < 8; i++) af[i] = As[kk][tr * 8 + i];
#pragma unroll
            for (int j = 0; j < 8; j++) bf[j] = Bs[kk][tc * 8 + j];
#pragma unroll
            for (int i = 0; i < 8; i++)
#pragma unroll
                for (int j = 0; j < 8; j++) acc[i][j] = fmaf(af[i], bf[j], acc[i][j]);
        }
        __syncthreads();
    }
    const float* b2e = b2 + (size_t)e * HDIM + n0;
#pragma unroll
    for (int i = 0; i < 8; i++) {
        int m = m0 + tr * 8 + i;
        if (m >= cnt) continue;
        int tok = g_list[e][m];
        float* dst = g_eo + (size_t)tok * HDIM + n0;
#pragma unroll
        for (int j = 0; j < 8; j++) {
            int n = tc * 8 + j;
            atomicAdd(&dst[n], acc[i][j] + b2e[n]);
        }
    }
}

// ---------------- LM head: g_eo @ lm_w + lm_b ----------------
__global__ __launch_bounds__(256, 2) void lm_kernel(const float* __restrict__ lw,
                                                    const float* __restrict__ lb,
                                                    float* __restrict__ out) {
    int m0 = blockIdx.y * 128;
    int n0 = blockIdx.x * 128;
    __shared__ float As[8][128];
    __shared__ float Bs[8][128];
    int tid = threadIdx.x;
    int a_m = tid >> 1;
    int a_k = (tid & 1) * 4;
    int b_k = tid >> 5;
    int b_n = (tid & 31) * 4;
    int tr = tid >> 4;
    int tc = tid & 15;
    const float* a_src = g_eo + (size_t)(m0 + a_m) * HDIM + a_k;

    float acc[8][8];
#pragma unroll
    for (int i = 0; i < 8; i++)
#pragma unroll
        for (int j = 0; j < 8; j++) acc[i][j] = 0.f;

    for (int k0 = 0; k0 < HDIM; k0 += 8) {
        float4 av = *(const float4*)(a_src + k0);
        As[a_k + 0][a_m] = av.x; As[a_k + 1][a_m] = av.y;
        As[a_k + 2][a_m] = av.z; As[a_k + 3][a_m] = av.w;
        *(float4*)&Bs[b_k][b_n] = *(const float4*)(lw + (size_t)(k0 + b_k) * VDIM + n0 + b_n);
        __syncthreads();
#pragma unroll
        for (int kk = 0; kk < 8; kk++) {
            float af[8], bf[8];
#pragma unroll
            for (int i = 0; i < 8; i++) af[i] = As[kk][tr * 8 + i];
#pragma unroll
            for (int j = 0; j < 8; j++) bf[j] = Bs[kk][tc * 8 + j];
#pragma unroll
            for (int i = 0; i < 8; i++)
#pragma unroll
                for (int j = 0; j < 8; j++) acc[i][j] = fmaf(af[i], bf[j], acc[i][j]);
        }
        __syncthreads();
    }
#pragma unroll
    for (int i = 0; i < 8; i++) {
        int m = m0 + tr * 8 + i;
        float* dst = out + (size_t)m * VDIM + n0;
#pragma unroll
        for (int j = 0; j < 8; j++) {
            int n = tc * 8 + j;
            dst[n] = acc[i][j] + lb[n0 + n];
        }
    }
}

extern "C" void kernel_launch(void* const* d_in, const int* in_sizes, int n_in,
                              void* d_out, int out_size) {
    const int*   ids = (const int*)d_in[0];
    const float* emb = (const float*)d_in[1];
    const float* rw  = (const float*)d_in[2];
    const float* rb  = (const float*)d_in[3];
    const float* w1  = (const float*)d_in[4];
    const float* b1  = (const float*)d_in[5];
    const float* w2  = (const float*)d_in[6];
    const float* b2  = (const float*)d_in[7];
    const float* lw  = (const float*)d_in[8];
    const float* lb  = (const float*)d_in[9];

    float* out = (float*)d_out;
    const size_t LOG = (size_t)TTOK * VDIM;
    float* out_rw = nullptr;
    float* out_se = nullptr;
    if ((size_t)out_size >= LOG + (size_t)2 * TTOK * KTOP) {
        out_rw = out + LOG;
        out_se = out + LOG + (size_t)TTOK * KTOP;
    }

    setup_kernel<<<TTOK, 128>>>(ids, emb, rw, rb, out_rw, out_se);
    build_lists_kernel<<<ENUM, 256>>>();
    zero_eo_kernel<<<(TTOK * HDIM / 4 + 255) / 256, 256>>>();
    ffn1_kernel<<<dim3(IDIM / 128, TTOK / 128, ENUM), 256>>>(w1, b1);
    ffn2_kernel<<<dim3(HDIM / 128, TTOK / 128, ENUM), 256>>>(w2, b2);
    lm_kernel<<<dim3(VDIM / 128, TTOK / 128), 256>>>(lw, lb, out);
}

// round 6
// speedup vs baseline: 3.7587x; 3.7587x over previous
#include <cuda_runtime.h>
#include <math.h>
#include <stdint.h>

#define TTOK 2048
#define HDIM 1024
#define ENUM 8
#define IDIM 4096
#define VDIM 32000
#define KTOP 2
#define KC   32

// ---- static scratch (no allocation allowed) ----
__device__ float g_x[(size_t)TTOK * HDIM];
__device__ float g_h[(size_t)ENUM * TTOK * IDIM];
__device__ float g_eo[(size_t)TTOK * HDIM];
__device__ int   g_sel[TTOK * KTOP];
__device__ int   g_list[ENUM][TTOK];
__device__ int   g_cnt[ENUM];

// ======================= helpers =======================
__device__ __forceinline__ uint32_t smem_u32(const void* p) {
    uint32_t a;
    asm("{ .reg .u64 t; cvta.to.shared.u64 t, %1; cvt.u32.u64 %0, t; }" : "=r"(a) : "l"(p));
    return a;
}
__device__ __forceinline__ uint32_t lds32(uint32_t a) {
    uint32_t v;
    asm volatile("ld.shared.b32 %0, [%1];" : "=r"(v) : "r"(a));
    return v;
}
// round-to-nearest fp32 -> tf32 (kills truncation bias in HMMA)
__device__ __forceinline__ uint32_t cvt_rna(uint32_t x) {
    uint32_t v;
    asm("cvt.rna.tf32.f32 %0, %1;" : "=r"(v) : "r"(x));
    return v;
}
#define CP16Z(dst, src, sz) \
    asm volatile("cp.async.cg.shared.global [%0], [%1], 16, %2;" \
                 :: "r"(dst), "l"(src), "r"(sz))
#define CPCOMMIT() asm volatile("cp.async.commit_group;")
#define CPWAIT(n)  asm volatile("cp.async.wait_group %0;" :: "n"(n))

#define MMA_TF32(d, a, b)                                                      \
    asm volatile(                                                              \
        "mma.sync.aligned.m16n8k8.row.col.f32.tf32.tf32.f32 "                  \
        "{%0,%1,%2,%3},{%4,%5,%6,%7},{%8,%9},{%0,%1,%2,%3};"                   \
        : "+f"((d)[0]), "+f"((d)[1]), "+f"((d)[2]), "+f"((d)[3])               \
        : "r"((a)[0]), "r"((a)[1]), "r"((a)[2]), "r"((a)[3]),                  \
          "r"((b)[0]), "r"((b)[1]))

// ======================= small kernels =======================
__global__ void setup_kernel(const int* __restrict__ ids,
                             const float* __restrict__ emb,
                             const float* __restrict__ rw,
                             const float* __restrict__ rb,
                             float* __restrict__ out_rw,
                             float* __restrict__ out_se) {
    int t = blockIdx.x;
    int tid = threadIdx.x;
    int row = ids[t];
    const float* src = emb + (size_t)row * HDIM;
    const float4* s4 = (const float4*)src;
    float4* d4 = (float4*)(g_x + (size_t)t * HDIM);
    for (int i = tid; i < HDIM / 4; i += blockDim.x) d4[i] = s4[i];

    float acc[ENUM];
#pragma unroll
    for (int e = 0; e < ENUM; e++) acc[e] = 0.f;
    for (int k = tid; k < HDIM; k += blockDim.x) {
        float xv = src[k];
        const float* wr = rw + (size_t)k * ENUM;
#pragma unroll
        for (int e = 0; e < ENUM; e++) acc[e] = fmaf(xv, wr[e], acc[e]);
    }
    __shared__ float sred[ENUM][128];
#pragma unroll
    for (int e = 0; e < ENUM; e++) sred[e][tid] = acc[e];
    __syncthreads();
    for (int s = 64; s > 0; s >>= 1) {
        if (tid < s) {
#pragma unroll
            for (int e = 0; e < ENUM; e++) sred[e][tid] += sred[e][tid + s];
        }
        __syncthreads();
    }
    if (tid == 0) {
        float lg[ENUM];
#pragma unroll
        for (int e = 0; e < ENUM; e++) lg[e] = sred[e][0] + rb[e];
        int i0 = 0; float v0 = lg[0];
#pragma unroll
        for (int e = 1; e < ENUM; e++) if (lg[e] > v0) { v0 = lg[e]; i0 = e; }
        int i1 = -1; float v1 = -3.0e38f;
#pragma unroll
        for (int e = 0; e < ENUM; e++) if (e != i0 && lg[e] > v1) { v1 = lg[e]; i1 = e; }
        float ee = expf(v1 - v0);
        float denom = 1.0f + ee;
        g_sel[t * 2 + 0] = i0;
        g_sel[t * 2 + 1] = i1;
        if (out_rw) { out_rw[t * 2 + 0] = 1.0f / denom; out_rw[t * 2 + 1] = ee / denom; }
        if (out_se) { out_se[t * 2 + 0] = (float)i0; out_se[t * 2 + 1] = (float)i1; }
    }
}

__global__ void build_lists_kernel() {
    int e = blockIdx.x;
    int tid = threadIdx.x;
    int lane = tid & 31, wid = tid >> 5;
    __shared__ int wtot[8];
    __shared__ int s_base;
    if (tid == 0) s_base = 0;
    __syncthreads();
    for (int base = 0; base < TTOK; base += 256) {
        int t = base + tid;
        int f = (g_sel[t * 2] == e || g_sel[t * 2 + 1] == e) ? 1 : 0;
        unsigned bal = __ballot_sync(0xffffffffu, f);
        int lpfx = __popc(bal & ((1u << lane) - 1u));
        if (lane == 0) wtot[wid] = __popc(bal);
        __syncthreads();
        int woff = 0;
        for (int w = 0; w < wid; w++) woff += wtot[w];
        if (f) g_list[e][s_base + woff + lpfx] = t;
        int tot = 0;
        for (int w = 0; w < 8; w++) tot += wtot[w];
        __syncthreads();
        if (tid == 0) s_base += tot;
        __syncthreads();
    }
    if (tid == 0) g_cnt[e] = s_base;
}

__global__ void zero_eo_kernel() {
    size_t i = (size_t)blockIdx.x * blockDim.x + threadIdx.x;
    if (i < (size_t)TTOK * HDIM / 4) {
        ((float4*)g_eo)[i] = make_float4(0.f, 0.f, 0.f, 0.f);
    }
}

// ======================= tf32 mma.sync GEMM =======================
// MODE 0: FFN1  gelu(Xg[e] @ w1[e] + b1[e]) -> g_h
// MODE 1: FFN2  (H[e] @ w2[e] + b2[e]) atomic-> g_eo
// MODE 2: LM    g_eo @ lm_w + lm_b -> out

#define SA 36                      // A smem row stride in floats (m-major)
#define SB 136                     // B smem row stride in floats (k-major)
#define AS_BYTES (128 * SA * 4)    // 18432
#define BS_BYTES (32 * SB * 4)     // 17408
#define BSOFF (2 * AS_BYTES)       // 36864
#define LISTOFF (BSOFF + 2 * BS_BYTES)  // 71680
#define SMEMSZ (LISTOFF + 512)          // 72192

template <int MODE>
__global__ void __launch_bounds__(256) gemm_mma(
    const float* __restrict__ Bglob,
    const float* __restrict__ bias,
    float* __restrict__ Out,
    int Ktot, int ldb)
{
    int e = blockIdx.z;
    int cnt = (MODE == 2) ? TTOK : g_cnt[e];
    int n0 = blockIdx.x * 128;
    int m0 = blockIdx.y * 128;
    if (m0 >= cnt) return;

    extern __shared__ char smem[];
    int* s_list = (int*)(smem + LISTOFF);
    uint32_t sbase = smem_u32(smem);

    int tid = threadIdx.x;
    int lane = tid & 31;
    int wid = tid >> 5;
    int wm = wid >> 2;       // 0..1  (m)
    int wn = wid & 3;        // 0..3  (n)

    const float* Bg;
    const float* be;
    if (MODE == 0)      { Bg = Bglob + (size_t)e * HDIM * IDIM; be = bias + (size_t)e * IDIM; }
    else if (MODE == 1) { Bg = Bglob + (size_t)e * IDIM * HDIM; be = bias + (size_t)e * HDIM; }
    else                { Bg = Bglob; be = bias; }

    if (MODE != 2 && tid < 128) {
        int gm = m0 + tid;
        s_list[tid] = (gm < cnt) ? g_list[e][gm] : -1;
    }
    __syncthreads();

    // ---- cp.async source/dest assignments ----
    int ac = tid & 7;
    int cb = tid & 31;
    const float* arow[4];
    uint32_t apred[4];
    uint32_t adst[4], bdst[4];
    int kb[4];
#pragma unroll
    for (int i = 0; i < 4; i++) {
        int r = (tid >> 3) + 32 * i;
        if (MODE == 0) {
            int tok = s_list[r];
            arow[i] = (tok >= 0) ? g_x + (size_t)tok * HDIM + ac * 4 : g_x;
            apred[i] = (tok >= 0) ? 16u : 0u;
        } else if (MODE == 1) {
            int gm = m0 + r;
            bool v = gm < cnt;
            arow[i] = v ? g_h + ((size_t)e * TTOK + gm) * IDIM + ac * 4 : g_h;
            apred[i] = v ? 16u : 0u;
        } else {
            arow[i] = g_eo + (size_t)(m0 + r) * HDIM + ac * 4;
            apred[i] = 16u;
        }
        adst[i] = sbase + (uint32_t)(r * SA * 4 + ac * 16);
        kb[i] = (tid >> 5) + 8 * i;
        bdst[i] = sbase + BSOFF + (uint32_t)(kb[i] * SB * 4 + cb * 16);
    }
    const float* bbase_g = Bg + n0 + cb * 4;

    float d[4][4][4];
#pragma unroll
    for (int i = 0; i < 4; i++)
#pragma unroll
        for (int j = 0; j < 4; j++)
#pragma unroll
            for (int r = 0; r < 4; r++) d[i][j][r] = 0.f;

    int nit = Ktot / KC;

    // prefetch tile 0 into buffer 0
#pragma unroll
    for (int i = 0; i < 4; i++) CP16Z(adst[i], arow[i], apred[i]);
#pragma unroll
    for (int i = 0; i < 4; i++) CP16Z(bdst[i], bbase_g + (size_t)kb[i] * ldb, 16u);
    CPCOMMIT();

    int ar_base = wm * 64 + (lane >> 2);
    int akc = lane & 3;
    int bnc = wn * 32 + (lane >> 2);

    for (int it = 0; it < nit; ++it) {
        int buf = it & 1;
        if (it + 1 < nit) {
            int nbuf = (it + 1) & 1;
            int k0 = (it + 1) * KC;
            uint32_t ao = (uint32_t)(nbuf * AS_BYTES);
            uint32_t bo = (uint32_t)(nbuf * BS_BYTES);
#pragma unroll
            for (int i = 0; i < 4; i++) CP16Z(adst[i] + ao, arow[i] + k0, apred[i]);
#pragma unroll
            for (int i = 0; i < 4; i++)
                CP16Z(bdst[i] + bo, bbase_g + (size_t)(k0 + kb[i]) * ldb, 16u);
            CPCOMMIT();
            CPWAIT(1);
        } else {
            CPWAIT(0);
        }
        __syncthreads();

        uint32_t abase = sbase + (uint32_t)(buf * AS_BYTES);
        uint32_t bbase = sbase + BSOFF + (uint32_t)(buf * BS_BYTES);
#pragma unroll
        for (int ks = 0; ks < 4; ks++) {
            int c0 = ks * 8 + akc;
            uint32_t a[4][4];
#pragma unroll
            for (int i = 0; i < 4; i++) {
                int r0 = ar_base + i * 16;
                a[i][0] = cvt_rna(lds32(abase + (uint32_t)((r0 * SA + c0) * 4)));
                a[i][1] = cvt_rna(lds32(abase + (uint32_t)(((r0 + 8) * SA + c0) * 4)));
                a[i][2] = cvt_rna(lds32(abase + (uint32_t)((r0 * SA + c0 + 4) * 4)));
                a[i][3] = cvt_rna(lds32(abase + (uint32_t)(((r0 + 8) * SA + c0 + 4) * 4)));
            }
            uint32_t b[4][2];
#pragma unroll
            for (int j = 0; j < 4; j++) {
                b[j][0] = cvt_rna(lds32(bbase + (uint32_t)((c0 * SB + bnc + j * 8) * 4)));
                b[j][1] = cvt_rna(lds32(bbase + (uint32_t)(((c0 + 4) * SB + bnc + j * 8) * 4)));
            }
#pragma unroll
            for (int i = 0; i < 4; i++)
#pragma unroll
                for (int j = 0; j < 4; j++) MMA_TF32(d[i][j], a[i], b[j]);
        }
        __syncthreads();
    }

    // ---- epilogue ----
    int row_l0 = wm * 64 + (lane >> 2);
    int col_l0 = wn * 32 + (lane & 3) * 2;
    float2 bj[4];
#pragma unroll
    for (int j = 0; j < 4; j++) {
        bj[j].x = be[n0 + col_l0 + j * 8];
        bj[j].y = be[n0 + col_l0 + j * 8 + 1];
    }

#pragma unroll
    for (int i = 0; i < 4; i++) {
        int rl = row_l0 + i * 16;
#pragma unroll
        for (int half = 0; half < 2; half++) {
            int r = rl + half * 8;
            int m = m0 + r;
            if (MODE != 2 && m >= cnt) continue;
#pragma unroll
            for (int j = 0; j < 4; j++) {
                int cl = col_l0 + j * 8;
                float v0 = d[i][j][half * 2 + 0] + bj[j].x;
                float v1 = d[i][j][half * 2 + 1] + bj[j].y;
                if (MODE == 0) {
                    v0 = 0.5f * v0 * (1.0f + erff(v0 * 0.70710678118654752f));
                    v1 = 0.5f * v1 * (1.0f + erff(v1 * 0.70710678118654752f));
                    float* dst = g_h + ((size_t)e * TTOK + m) * IDIM + n0 + cl;
                    *(float2*)dst = make_float2(v0, v1);
                } else if (MODE == 1) {
                    int tok = s_list[r];
                    float* dst = g_eo + (size_t)tok * HDIM + n0 + cl;
                    atomicAdd(dst + 0, v0);
                    atomicAdd(dst + 1, v1);
                } else {
                    float* dst = Out + (size_t)m * VDIM + n0 + cl;
                    *(float2*)dst = make_float2(v0, v1);
                }
            }
        }
    }
}

// ======================= launcher =======================
extern "C" void kernel_launch(void* const* d_in, const int* in_sizes, int n_in,
                              void* d_out, int out_size) {
    const int*   ids = (const int*)d_in[0];
    const float* emb = (const float*)d_in[1];
    const float* rw  = (const float*)d_in[2];
    const float* rb  = (const float*)d_in[3];
    const float* w1  = (const float*)d_in[4];
    const float* b1  = (const float*)d_in[5];
    const float* w2  = (const float*)d_in[6];
    const float* b2  = (const float*)d_in[7];
    const float* lw  = (const float*)d_in[8];
    const float* lb  = (const float*)d_in[9];

    float* out = (float*)d_out;
    const size_t LOG = (size_t)TTOK * VDIM;
    float* out_rw = nullptr;
    float* out_se = nullptr;
    if ((size_t)out_size >= LOG + (size_t)2 * TTOK * KTOP) {
        out_rw = out + LOG;
        out_se = out + LOG + (size_t)TTOK * KTOP;
    }

    static bool attr_done = false;
    if (!attr_done) {
        cudaFuncSetAttribute(gemm_mma<0>, cudaFuncAttributeMaxDynamicSharedMemorySize, SMEMSZ);
        cudaFuncSetAttribute(gemm_mma<1>, cudaFuncAttributeMaxDynamicSharedMemorySize, SMEMSZ);
        cudaFuncSetAttribute(gemm_mma<2>, cudaFuncAttributeMaxDynamicSharedMemorySize, SMEMSZ);
        attr_done = true;
    }

    setup_kernel<<<TTOK, 128>>>(ids, emb, rw, rb, out_rw, out_se);
    build_lists_kernel<<<ENUM, 256>>>();
    zero_eo_kernel<<<(TTOK * HDIM / 4 + 255) / 256, 256>>>();
    gemm_mma<0><<<dim3(IDIM / 128, TTOK / 128, ENUM), 256, SMEMSZ>>>(w1, b1, nullptr, HDIM, IDIM);
    gemm_mma<1><<<dim3(HDIM / 128, TTOK / 128, ENUM), 256, SMEMSZ>>>(w2, b2, nullptr, IDIM, HDIM);
    gemm_mma<2><<<dim3(VDIM / 128, TTOK / 128, 1), 256, SMEMSZ>>>(lw, lb, out, HDIM, VDIM);
}